// round 1
// baseline (speedup 1.0000x reference)
#include <cuda_runtime.h>
#include <cfloat>
#include <math.h>

// ---------------------------------------------------------------------------
// VectorQuantizer: y, idx, loss, perplexity, usage, H
//   x:        [65536, 256] f32 (flattened from [64,32,32,256])
//   codebook: [1024, 256]  f32
// Output layout (adaptive on out_size):
//   [ y (N*D) | idx as float (N) | loss | perplexity | usage | H ]
// ---------------------------------------------------------------------------

#define N_FIXED 65536
#define D 256
#define D4 64           // D / 4
#define KCB 1024
#define BN 128          // rows per block in argmin kernel
#define XS_STRIDE4 65   // x smem row stride in float4 (260 floats)
#define CS_STRIDE 132   // code smem row stride in floats (128 + 4 pad)
#define SMEM_FLOATS (128 * 260 + 2 * 32 * CS_STRIDE + 1024)

// ---- scratch (device globals; no allocations allowed) ----
__device__ int          g_idx[N_FIXED];
__device__ float        g_e2[KCB];
__device__ unsigned int g_counts[KCB];
__device__ double       g_partial[N_FIXED / 4];   // per gather-block SSE partials

// ---------------------------------------------------------------------------
// init: zero histogram
// ---------------------------------------------------------------------------
__global__ void vq_init_kernel() {
    int t = threadIdx.x;
    if (t < KCB) g_counts[t] = 0u;
}

// ---------------------------------------------------------------------------
// e2[k] = sum_d codebook[k][d]^2   (warp per row)
// ---------------------------------------------------------------------------
__global__ void vq_e2_kernel(const float* __restrict__ cb) {
    int row  = blockIdx.x * 8 + (threadIdx.x >> 5);
    int lane = threadIdx.x & 31;
    float s = 0.0f;
#pragma unroll
    for (int j = 0; j < 8; ++j) {
        float v = cb[row * D + lane + j * 32];
        s = fmaf(v, v, s);
    }
#pragma unroll
    for (int m = 16; m >= 1; m >>= 1)
        s += __shfl_xor_sync(0xffffffffu, s, m);
    if (lane == 0) g_e2[row] = s;
}

// ---------------------------------------------------------------------------
// Fused argmin GEMM.
//   Block: 128 rows x full K=1024.  Threads 256 = 16(tx: codes) x 16(ty: rows).
//   Per thread: 8 rows x 8 codes register tile.
//   dist replicates reference rounding:  fl( fl(x2 + e2) - fl(2*sim) )
//   Tie-breaking: first (lowest) index, matching jnp.argmin.
// ---------------------------------------------------------------------------
__global__ void __launch_bounds__(256, 1)
vq_argmin_kernel(const float* __restrict__ x, const float* __restrict__ cb) {
    extern __shared__ float smem[];
    float* xs  = smem;                       // 128*260 floats (float4-swizzled)
    float* cs  = smem + 128 * 260;           // 2 buffers of 32*CS_STRIDE
    float* e2s = cs + 2 * 32 * CS_STRIDE;    // 1024

    const int tid = threadIdx.x;
    const int tx  = tid & 15;
    const int ty  = tid >> 4;
    const int n0  = blockIdx.x * BN;

    // stage e2 into smem
    for (int i = tid; i < KCB; i += 256) e2s[i] = g_e2[i];

    // load x tile (swizzled so 8-apart rows hit different banks)
    const float4* __restrict__ x4 = (const float4*)x;
    float4* xs4 = (float4*)xs;
#pragma unroll
    for (int u = 0; u < 32; ++u) {
        int f  = tid + u * 256;        // 0..8191
        int r  = f >> 6;
        int d4 = f & 63;
        float4 v = x4[(size_t)(n0 + r) * D4 + d4];
        xs4[r * XS_STRIDE4 + (d4 ^ ((r >> 3) & 7))] = v;
    }
    __syncthreads();

    // x2 per row (16 lanes each sum 16 elements, then butterfly over 16)
    float x2r[8];
#pragma unroll
    for (int i = 0; i < 8; ++i) {
        int r  = ty * 8 + i;
        int sw = (r >> 3) & 7;
        float s = 0.0f;
#pragma unroll
        for (int q = 0; q < 4; ++q) {
            float4 v = xs4[r * XS_STRIDE4 + ((tx * 4 + q) ^ sw)];
            s = fmaf(v.x, v.x, s);
            s = fmaf(v.y, v.y, s);
            s = fmaf(v.z, v.z, s);
            s = fmaf(v.w, v.w, s);
        }
#pragma unroll
        for (int m = 8; m >= 1; m >>= 1)
            s += __shfl_xor_sync(0xffffffffu, s, m, 16);
        x2r[i] = s;
    }

    float rbd[8];
    int   rbk[8];
#pragma unroll
    for (int i = 0; i < 8; ++i) { rbd[i] = FLT_MAX; rbk[i] = 0; }

    const float4* __restrict__ cb4 = (const float4*)cb;

    // preload chunk 0 (kt=0, dt=0) into buffer 0, transposed [dd][k]
    {
        float* dst = cs;
#pragma unroll
        for (int u = 0; u < 4; ++u) {
            int f   = tid + u * 256;   // 0..1023
            int kl  = f >> 3;
            int dl4 = f & 7;
            float4 v = cb4[(size_t)kl * D4 + dl4];
            int ddb = dl4 * 4;
            dst[(ddb + 0) * CS_STRIDE + kl] = v.x;
            dst[(ddb + 1) * CS_STRIDE + kl] = v.y;
            dst[(ddb + 2) * CS_STRIDE + kl] = v.z;
            dst[(ddb + 3) * CS_STRIDE + kl] = v.w;
        }
    }
    __syncthreads();

    float sim[8][8];

#pragma unroll 1
    for (int cc = 0; cc < 64; ++cc) {      // chunk = (kt = cc>>3, dt = cc&7)
        const int kt = cc >> 3;
        const int dt = cc & 7;

        if (dt == 0) {
#pragma unroll
            for (int i = 0; i < 8; ++i)
#pragma unroll
                for (int j = 0; j < 8; ++j) sim[i][j] = 0.0f;
        }

        // prefetch next chunk into registers (overlaps with compute)
        float4 pv[4];
        const bool have_next = (cc < 63);
        if (have_next) {
            int nkt = (cc + 1) >> 3, ndt = (cc + 1) & 7;
#pragma unroll
            for (int u = 0; u < 4; ++u) {
                int f   = tid + u * 256;
                int kl  = f >> 3;
                int dl4 = f & 7;
                pv[u] = cb4[(size_t)(nkt * 128 + kl) * D4 + ndt * 8 + dl4];
            }
        }

        // compute: sim[i][j] += x[r_i][d] * cb[k_j][d] over this 32-d chunk
        const float4* csb4 = (const float4*)(cs + (cc & 1) * (32 * CS_STRIDE));
#pragma unroll
        for (int dd4 = 0; dd4 < 8; ++dd4) {
            float4 xv[8];
#pragma unroll
            for (int i = 0; i < 8; ++i) {
                int r = ty * 8 + i;
                xv[i] = xs4[r * XS_STRIDE4 + ((dt * 8 + dd4) ^ ((r >> 3) & 7))];
            }
#pragma unroll
            for (int t = 0; t < 4; ++t) {
                int dd = dd4 * 4 + t;
                float4 ca = csb4[dd * 33 + tx * 2];
                float4 cb_ = csb4[dd * 33 + tx * 2 + 1];
#pragma unroll
                for (int i = 0; i < 8; ++i) {
                    float xv_s = (t == 0) ? xv[i].x : (t == 1) ? xv[i].y
                               : (t == 2) ? xv[i].z : xv[i].w;
                    sim[i][0] = fmaf(xv_s, ca.x,  sim[i][0]);
                    sim[i][1] = fmaf(xv_s, ca.y,  sim[i][1]);
                    sim[i][2] = fmaf(xv_s, ca.z,  sim[i][2]);
                    sim[i][3] = fmaf(xv_s, ca.w,  sim[i][3]);
                    sim[i][4] = fmaf(xv_s, cb_.x, sim[i][4]);
                    sim[i][5] = fmaf(xv_s, cb_.y, sim[i][5]);
                    sim[i][6] = fmaf(xv_s, cb_.z, sim[i][6]);
                    sim[i][7] = fmaf(xv_s, cb_.w, sim[i][7]);
                }
            }
        }

        // store prefetched chunk into the other buffer
        if (have_next) {
            float* dst = cs + ((cc + 1) & 1) * (32 * CS_STRIDE);
#pragma unroll
            for (int u = 0; u < 4; ++u) {
                int f   = tid + u * 256;
                int kl  = f >> 3;
                int ddb = (f & 7) * 4;
                dst[(ddb + 0) * CS_STRIDE + kl] = pv[u].x;
                dst[(ddb + 1) * CS_STRIDE + kl] = pv[u].y;
                dst[(ddb + 2) * CS_STRIDE + kl] = pv[u].z;
                dst[(ddb + 3) * CS_STRIDE + kl] = pv[u].w;
            }
        }

        // epilogue once per k-tile (after last d chunk)
        if (dt == 7) {
#pragma unroll
            for (int i = 0; i < 8; ++i) {
                float tbd = FLT_MAX;
                int   tbk = 0;
#pragma unroll
                for (int j = 0; j < 8; ++j) {
                    int k = kt * 128 + tx * 8 + j;
                    float t1   = __fadd_rn(x2r[i], e2s[k]);
                    float dst_ = __fadd_rn(t1, -__fmul_rn(2.0f, sim[i][j]));
                    if (dst_ < tbd) { tbd = dst_; tbk = k; }   // first min wins
                }
#pragma unroll
                for (int m = 1; m < 16; m <<= 1) {
                    float od = __shfl_xor_sync(0xffffffffu, tbd, m, 16);
                    int   ok = __shfl_xor_sync(0xffffffffu, tbk, m, 16);
                    if (od < tbd || (od == tbd && ok < tbk)) { tbd = od; tbk = ok; }
                }
                if (tbd < rbd[i]) { rbd[i] = tbd; rbk[i] = tbk; } // earlier kt wins ties
            }
        }
        __syncthreads();
    }

    if (tx == 0) {
#pragma unroll
        for (int i = 0; i < 8; ++i)
            g_idx[n0 + ty * 8 + i] = rbk[i];
    }
}

// ---------------------------------------------------------------------------
// gather: y = fl(x + fl(q - x)) (matches straight-through numerics exactly),
// per-block deterministic f64 SSE partials, histogram, idx-as-float output.
// Block = 256 threads = 4 rows x 64 float4 columns.
// ---------------------------------------------------------------------------
__global__ void __launch_bounds__(256)
vq_gather_kernel(const float* __restrict__ x, const float* __restrict__ cb,
                 float* __restrict__ y_out, float* __restrict__ idxf_out) {
    __shared__ double red[256];
    int tid = threadIdx.x;
    int n   = blockIdx.x * 4 + (tid >> 6);
    int d4  = tid & 63;
    int k   = g_idx[n];

    const float4* x4  = (const float4*)x;
    const float4* cb4 = (const float4*)cb;
    float4 xv = x4[(size_t)n * D4 + d4];
    float4 qv = cb4[(size_t)k * D4 + d4];

    float tx_ = __fadd_rn(qv.x, -xv.x);
    float ty_ = __fadd_rn(qv.y, -xv.y);
    float tz_ = __fadd_rn(qv.z, -xv.z);
    float tw_ = __fadd_rn(qv.w, -xv.w);

    float4 yv;
    yv.x = __fadd_rn(xv.x, tx_);
    yv.y = __fadd_rn(xv.y, ty_);
    yv.z = __fadd_rn(xv.z, tz_);
    yv.w = __fadd_rn(xv.w, tw_);
    ((float4*)y_out)[(size_t)n * D4 + d4] = yv;

    double s = (double)tx_ * tx_ + (double)ty_ * ty_ +
               (double)tz_ * tz_ + (double)tw_ * tw_;
    red[tid] = s;
    __syncthreads();
#pragma unroll
    for (int m = 128; m >= 1; m >>= 1) {
        if (tid < m) red[tid] += red[tid + m];
        __syncthreads();
    }
    if (tid == 0) g_partial[blockIdx.x] = red[0];

    if (d4 == 0) {
        atomicAdd(&g_counts[k], 1u);
        if (idxf_out) idxf_out[n] = (float)k;
    }
}

// ---------------------------------------------------------------------------
// finalize: loss = 1.25*mse (commit == codebook term numerically),
// H = -sum p*log2(p+1e-10), perplexity = exp(H*ln2), usage.
// ---------------------------------------------------------------------------
__global__ void __launch_bounds__(1024)
vq_finalize_kernel(float* __restrict__ scal_out, int nblocks_gather) {
    __shared__ double redH[1024];
    __shared__ double redU[1024];
    __shared__ double redS[1024];
    int t = threadIdx.x;

    double s = 0.0;
    for (int i = t; i < nblocks_gather; i += 1024) s += g_partial[i];

    float p    = (float)g_counts[t] * (1.0f / 65536.0f);
    float term = p * log2f(p + 1e-10f);

    redH[t] = -(double)term;
    redU[t] = (p > 0.0f) ? 1.0 : 0.0;
    redS[t] = s;
    __syncthreads();
#pragma unroll
    for (int m = 512; m >= 1; m >>= 1) {
        if (t < m) {
            redH[t] += redH[t + m];
            redU[t] += redU[t + m];
            redS[t] += redS[t + m];
        }
        __syncthreads();
    }
    if (t == 0) {
        double mse = redS[0] / (double)((size_t)N_FIXED * D);
        float  c    = (float)mse;
        float  loss = __fadd_rn(__fmul_rn(0.25f, c), c);
        float  H    = (float)redH[0];
        float  perp = expf(__fmul_rn(H, 0.69314718f));
        float  usage = (float)(redU[0] / 1024.0);
        scal_out[0] = loss;
        scal_out[1] = perp;
        scal_out[2] = usage;
        scal_out[3] = H;
    }
}

// ---------------------------------------------------------------------------
extern "C" void kernel_launch(void* const* d_in, const int* in_sizes, int n_in,
                              void* d_out, int out_size) {
    (void)n_in;
    const float* x  = (const float*)d_in[0];
    const float* cb = (const float*)d_in[1];
    float* out = (float*)d_out;

    const int    n  = in_sizes[0] / D;      // 65536
    const size_t ND = (size_t)n * D;

    const long long os = (long long)out_size;
    const int with_idx  = os >= (long long)(ND + (size_t)n);
    const int with_scal = os >= (long long)(ND + (size_t)n + 4);

    const size_t smem_bytes = (size_t)SMEM_FLOATS * sizeof(float);
    cudaFuncSetAttribute(vq_argmin_kernel,
                         cudaFuncAttributeMaxDynamicSharedMemorySize,
                         (int)smem_bytes);

    vq_init_kernel<<<1, 1024>>>();
    vq_e2_kernel<<<KCB / 8, 256>>>(cb);
    vq_argmin_kernel<<<n / BN, 256, smem_bytes>>>(x, cb);
    vq_gather_kernel<<<n / 4, 256>>>(x, cb, out,
                                     with_idx ? (out + ND) : (float*)0);
    if (with_scal)
        vq_finalize_kernel<<<1, 1024>>>(out + ND + n, n / 4);
}

// round 2
// speedup vs baseline: 1.5076x; 1.5076x over previous
#include <cuda_runtime.h>
#include <cfloat>
#include <math.h>

// ---------------------------------------------------------------------------
// VectorQuantizer: y, idx, loss, perplexity, usage, H
//   x:        [65536, 256] f32,  codebook: [1024, 256] f32
// Output: [ y (N*D) | idx as float (N) | loss | perplexity | usage | H ]
// R2: FFMA2 (fma.rn.f32x2) mainloop (2x fp32 FMA/slot, bit-identical RN),
//     warp-parallel gather with single-barrier reduction.
// ---------------------------------------------------------------------------

#define N_FIXED 65536
#define D 256
#define D4 64
#define KCB 1024
#define BN 128
#define XS_STRIDE4 65   // x smem row stride in float4
#define CS_STRIDE 132   // code smem row stride in floats (33 x 16B)
#define SMEM_FLOATS (128 * 260 + 2 * 32 * CS_STRIDE + 1024)

__device__ int          g_idx[N_FIXED];
__device__ float        g_e2[KCB];
__device__ unsigned int g_counts[KCB];
__device__ double       g_partial[2048];

// packed fp32x2 FMA: d = a*b + d (lanewise, round-to-nearest; identical to scalar)
#define FMA2(d, a, b) \
    asm("fma.rn.f32x2 %0, %1, %2, %0;" : "+l"(d) : "l"(a), "l"(b))

__device__ __forceinline__ unsigned long long bcast2(float v) {
    unsigned long long r;
    asm("mov.b64 %0, {%1, %1};" : "=l"(r) : "f"(v));
    return r;
}

// ---------------------------------------------------------------------------
__global__ void vq_init_kernel() {
    int t = threadIdx.x;
    if (t < KCB) g_counts[t] = 0u;
}

__global__ void vq_e2_kernel(const float* __restrict__ cb) {
    int row  = blockIdx.x * 8 + (threadIdx.x >> 5);
    int lane = threadIdx.x & 31;
    float s = 0.0f;
#pragma unroll
    for (int j = 0; j < 8; ++j) {
        float v = cb[row * D + lane + j * 32];
        s = fmaf(v, v, s);
    }
#pragma unroll
    for (int m = 16; m >= 1; m >>= 1)
        s += __shfl_xor_sync(0xffffffffu, s, m);
    if (lane == 0) g_e2[row] = s;
}

// ---------------------------------------------------------------------------
// Fused argmin GEMM: 128 rows x 1024 codes per block, 256 thr, 8x8 reg tile,
// accumulators packed as f32x2 pairs along the code axis.
// dist = fl( fl(x2+e2) - fl(2*sim) ), first-index tie-break (jnp.argmin).
// ---------------------------------------------------------------------------
__global__ void __launch_bounds__(256, 1)
vq_argmin_kernel(const float* __restrict__ x, const float* __restrict__ cb) {
    extern __shared__ float smem[];
    float* xs  = smem;                       // 128*260 floats
    float* cs  = smem + 128 * 260;           // 2 buffers of 32*CS_STRIDE
    float* e2s = cs + 2 * 32 * CS_STRIDE;    // 1024

    const int tid = threadIdx.x;
    const int tx  = tid & 15;
    const int ty  = tid >> 4;
    const int n0  = blockIdx.x * BN;

    for (int i = tid; i < KCB; i += 256) e2s[i] = g_e2[i];

    const float4* __restrict__ x4 = (const float4*)x;
    float4* xs4 = (float4*)xs;
#pragma unroll
    for (int u = 0; u < 32; ++u) {
        int f  = tid + u * 256;
        int r  = f >> 6;
        int d4 = f & 63;
        float4 v = x4[(size_t)(n0 + r) * D4 + d4];
        xs4[r * XS_STRIDE4 + (d4 ^ ((r >> 3) & 7))] = v;
    }
    __syncthreads();

    // x2 per row
    float x2r[8];
#pragma unroll
    for (int i = 0; i < 8; ++i) {
        int r  = ty * 8 + i;
        int sw = (r >> 3) & 7;
        float s = 0.0f;
#pragma unroll
        for (int q = 0; q < 4; ++q) {
            float4 v = xs4[r * XS_STRIDE4 + ((tx * 4 + q) ^ sw)];
            s = fmaf(v.x, v.x, s);
            s = fmaf(v.y, v.y, s);
            s = fmaf(v.z, v.z, s);
            s = fmaf(v.w, v.w, s);
        }
#pragma unroll
        for (int m = 8; m >= 1; m >>= 1)
            s += __shfl_xor_sync(0xffffffffu, s, m, 16);
        x2r[i] = s;
    }

    float rbd[8];
    int   rbk[8];
#pragma unroll
    for (int i = 0; i < 8; ++i) { rbd[i] = FLT_MAX; rbk[i] = 0; }

    const float4* __restrict__ cb4 = (const float4*)cb;

    // preload chunk 0 (kt=0, dt=0), transposed [dd][k]
    {
        float* dst = cs;
#pragma unroll
        for (int u = 0; u < 4; ++u) {
            int f   = tid + u * 256;
            int kl  = f >> 3;
            int dl4 = f & 7;
            float4 v = cb4[(size_t)kl * D4 + dl4];
            int ddb = dl4 * 4;
            dst[(ddb + 0) * CS_STRIDE + kl] = v.x;
            dst[(ddb + 1) * CS_STRIDE + kl] = v.y;
            dst[(ddb + 2) * CS_STRIDE + kl] = v.z;
            dst[(ddb + 3) * CS_STRIDE + kl] = v.w;
        }
    }
    __syncthreads();

    unsigned long long simp[8][4];   // 8 rows x 4 code-pairs (f32x2)

#pragma unroll 1
    for (int cc = 0; cc < 64; ++cc) {      // kt = cc>>3, dt = cc&7
        const int kt = cc >> 3;
        const int dt = cc & 7;

        if (dt == 0) {
#pragma unroll
            for (int i = 0; i < 8; ++i)
#pragma unroll
                for (int j = 0; j < 4; ++j) simp[i][j] = 0ull;
        }

        // prefetch next chunk into registers
        float4 pv[4];
        const bool have_next = (cc < 63);
        if (have_next) {
            int nkt = (cc + 1) >> 3, ndt = (cc + 1) & 7;
#pragma unroll
            for (int u = 0; u < 4; ++u) {
                int f   = tid + u * 256;
                int kl  = f >> 3;
                int dl4 = f & 7;
                pv[u] = cb4[(size_t)(nkt * 128 + kl) * D4 + ndt * 8 + dl4];
            }
        }

        // mainloop over this 32-d chunk
        const ulonglong2* csb2 =
            (const ulonglong2*)(cs + (cc & 1) * (32 * CS_STRIDE));
#pragma unroll
        for (int dd4 = 0; dd4 < 8; ++dd4) {
            float4 xv[8];
#pragma unroll
            for (int i = 0; i < 8; ++i) {
                int r = ty * 8 + i;
                xv[i] = xs4[r * XS_STRIDE4 + ((dt * 8 + dd4) ^ ((r >> 3) & 7))];
            }
#pragma unroll
            for (int t = 0; t < 4; ++t) {
                int dd = dd4 * 4 + t;
                ulonglong2 c01 = csb2[dd * 33 + tx * 2];       // codes 0-3
                ulonglong2 c23 = csb2[dd * 33 + tx * 2 + 1];   // codes 4-7
#pragma unroll
                for (int i = 0; i < 8; ++i) {
                    float xv_s = (t == 0) ? xv[i].x : (t == 1) ? xv[i].y
                               : (t == 2) ? xv[i].z : xv[i].w;
                    unsigned long long xp = bcast2(xv_s);
                    FMA2(simp[i][0], xp, c01.x);
                    FMA2(simp[i][1], xp, c01.y);
                    FMA2(simp[i][2], xp, c23.x);
                    FMA2(simp[i][3], xp, c23.y);
                }
            }
        }

        if (have_next) {
            float* dst = cs + ((cc + 1) & 1) * (32 * CS_STRIDE);
#pragma unroll
            for (int u = 0; u < 4; ++u) {
                int f   = tid + u * 256;
                int kl  = f >> 3;
                int ddb = (f & 7) * 4;
                dst[(ddb + 0) * CS_STRIDE + kl] = pv[u].x;
                dst[(ddb + 1) * CS_STRIDE + kl] = pv[u].y;
                dst[(ddb + 2) * CS_STRIDE + kl] = pv[u].z;
                dst[(ddb + 3) * CS_STRIDE + kl] = pv[u].w;
            }
        }

        // epilogue per k-tile
        if (dt == 7) {
#pragma unroll
            for (int i = 0; i < 8; ++i) {
                float tbd = FLT_MAX;
                int   tbk = 0;
#pragma unroll
                for (int jp = 0; jp < 4; ++jp) {
                    unsigned long long s = simp[i][jp];
                    float s0 = __uint_as_float((unsigned)s);
                    float s1 = __uint_as_float((unsigned)(s >> 32));
                    int k0 = kt * 128 + tx * 8 + jp * 2;
                    float t1 = __fadd_rn(x2r[i], e2s[k0]);
                    float d0 = __fadd_rn(t1, -__fmul_rn(2.0f, s0));
                    if (d0 < tbd) { tbd = d0; tbk = k0; }
                    float t2 = __fadd_rn(x2r[i], e2s[k0 + 1]);
                    float d1 = __fadd_rn(t2, -__fmul_rn(2.0f, s1));
                    if (d1 < tbd) { tbd = d1; tbk = k0 + 1; }
                }
#pragma unroll
                for (int m = 1; m < 16; m <<= 1) {
                    float od = __shfl_xor_sync(0xffffffffu, tbd, m, 16);
                    int   ok = __shfl_xor_sync(0xffffffffu, tbk, m, 16);
                    if (od < tbd || (od == tbd && ok < tbk)) { tbd = od; tbk = ok; }
                }
                if (tbd < rbd[i]) { rbd[i] = tbd; rbk[i] = tbk; }
            }
        }
        __syncthreads();
    }

    if (tx == 0) {
#pragma unroll
        for (int i = 0; i < 8; ++i)
            g_idx[n0 + ty * 8 + i] = rbk[i];
    }
}

// ---------------------------------------------------------------------------
// gather: warp per 4 rows, 32 rows per block (2048 blocks), one barrier.
// y = fl(x + fl(q - x)); deterministic f64 partials; histogram; idx output.
// ---------------------------------------------------------------------------
__global__ void __launch_bounds__(256)
vq_gather_kernel(const float* __restrict__ x, const float* __restrict__ cb,
                 float* __restrict__ y_out, float* __restrict__ idxf_out) {
    __shared__ double wsum[8];
    const int tid  = threadIdx.x;
    const int wid  = tid >> 5;
    const int lane = tid & 31;
    const int nb   = blockIdx.x * 32 + wid * 4;

    int k4[4];
#pragma unroll
    for (int rr = 0; rr < 4; ++rr) k4[rr] = g_idx[nb + rr];

    const float4* x4  = (const float4*)x;
    const float4* cb4 = (const float4*)cb;
    float4* y4 = (float4*)y_out;

    double acc = 0.0;
#pragma unroll
    for (int rr = 0; rr < 4; ++rr) {
        int n = nb + rr;
        int k = k4[rr];
#pragma unroll
        for (int u = 0; u < 2; ++u) {
            int d4 = lane + u * 32;
            float4 xv = x4[(size_t)n * D4 + d4];
            float4 qv = cb4[(size_t)k * D4 + d4];
            float tx_ = __fadd_rn(qv.x, -xv.x);
            float ty_ = __fadd_rn(qv.y, -xv.y);
            float tz_ = __fadd_rn(qv.z, -xv.z);
            float tw_ = __fadd_rn(qv.w, -xv.w);
            float4 yv;
            yv.x = __fadd_rn(xv.x, tx_);
            yv.y = __fadd_rn(xv.y, ty_);
            yv.z = __fadd_rn(xv.z, tz_);
            yv.w = __fadd_rn(xv.w, tw_);
            y4[(size_t)n * D4 + d4] = yv;
            acc += (double)tx_ * tx_ + (double)ty_ * ty_ +
                   (double)tz_ * tz_ + (double)tw_ * tw_;
        }
        if (lane == 0) {
            atomicAdd(&g_counts[k], 1u);
            if (idxf_out) idxf_out[n] = (float)k;
        }
    }

#pragma unroll
    for (int m = 16; m >= 1; m >>= 1)
        acc += __shfl_xor_sync(0xffffffffu, acc, m);
    if (lane == 0) wsum[wid] = acc;
    __syncthreads();
    if (tid == 0) {
        double s = 0.0;
#pragma unroll
        for (int i = 0; i < 8; ++i) s += wsum[i];
        g_partial[blockIdx.x] = s;
    }
}

// ---------------------------------------------------------------------------
__global__ void __launch_bounds__(1024)
vq_finalize_kernel(float* __restrict__ scal_out, int nblocks_gather) {
    __shared__ double redH[1024];
    __shared__ double redU[1024];
    __shared__ double redS[1024];
    int t = threadIdx.x;

    double s = 0.0;
    for (int i = t; i < nblocks_gather; i += 1024) s += g_partial[i];

    float p    = (float)g_counts[t] * (1.0f / 65536.0f);
    float term = p * log2f(p + 1e-10f);

    redH[t] = -(double)term;
    redU[t] = (p > 0.0f) ? 1.0 : 0.0;
    redS[t] = s;
    __syncthreads();
#pragma unroll
    for (int m = 512; m >= 1; m >>= 1) {
        if (t < m) {
            redH[t] += redH[t + m];
            redU[t] += redU[t + m];
            redS[t] += redS[t + m];
        }
        __syncthreads();
    }
    if (t == 0) {
        double mse = redS[0] / (double)((size_t)N_FIXED * D);
        float  c     = (float)mse;
        float  loss  = __fadd_rn(__fmul_rn(0.25f, c), c);
        float  H     = (float)redH[0];
        float  perp  = expf(__fmul_rn(H, 0.69314718f));
        float  usage = (float)(redU[0] / 1024.0);
        scal_out[0] = loss;
        scal_out[1] = perp;
        scal_out[2] = usage;
        scal_out[3] = H;
    }
}

// ---------------------------------------------------------------------------
extern "C" void kernel_launch(void* const* d_in, const int* in_sizes, int n_in,
                              void* d_out, int out_size) {
    (void)n_in;
    const float* x  = (const float*)d_in[0];
    const float* cb = (const float*)d_in[1];
    float* out = (float*)d_out;

    const int    n  = in_sizes[0] / D;      // 65536
    const size_t ND = (size_t)n * D;

    const long long os = (long long)out_size;
    const int with_idx  = os >= (long long)(ND + (size_t)n);
    const int with_scal = os >= (long long)(ND + (size_t)n + 4);

    const size_t smem_bytes = (size_t)SMEM_FLOATS * sizeof(float);
    cudaFuncSetAttribute(vq_argmin_kernel,
                         cudaFuncAttributeMaxDynamicSharedMemorySize,
                         (int)smem_bytes);

    vq_init_kernel<<<1, 1024>>>();
    vq_e2_kernel<<<KCB / 8, 256>>>(cb);
    vq_argmin_kernel<<<n / BN, 256, smem_bytes>>>(x, cb);
    vq_gather_kernel<<<n / 32, 256>>>(x, cb, out,
                                      with_idx ? (out + ND) : (float*)0);
    if (with_scal)
        vq_finalize_kernel<<<1, 1024>>>(out + ND + n, n / 32);
}